// round 3
// baseline (speedup 1.0000x reference)
#include <cuda_runtime.h>
#include <cuda_fp16.h>

#define PH 7
#define PW 7
#define SP 4
#define CH 10
#define FH 34
#define FW 34
#define NPIX (FH * FW)      // 1156
#define NBINS (PH * PW)     // 49
#define TPB 256
#define RPT 4               // rois per thread
#define RPB (TPB * RPT)     // rois per block = 1024
#define PADC 16             // halves per pixel slot (10 used), 32B stride
#define SCRN 10240          // scratch column stride (max N padded)

// 490 x 10240 f32 scratch, layout scratch[(c*49+bin)*SCRN + n]  (~20 MB)
__device__ float g_scratch[CH * NBINS * SCRN];

__global__ void __launch_bounds__(TPB) psroi_kernel(
    const float* __restrict__ ft,     // (C*49, 34, 34)
    const float* __restrict__ rois,   // (N, 5)
    int N)
{
    __shared__ __align__(16) __half sm[NPIX * PADC];   // 36,992 B

    const int bin = blockIdx.y;            // ph*7 + pw
    const int ph  = bin / PW;
    const int pw  = bin - ph * PW;
    const int tid = threadIdx.x;

    // ---- Stage the (ph,pw) slice, all 10 channels, as fp16 [pix][c] ----
    {
        const float* base = ft + (size_t)bin * NPIX;
        for (int p = tid; p < NPIX; p += TPB) {
            unsigned int h2[5];
            #pragma unroll
            for (int c = 0; c < 5; ++c) {
                float a = base[(size_t)(2 * c)     * (NBINS * NPIX) + p];
                float b = base[(size_t)(2 * c + 1) * (NBINS * NPIX) + p];
                __half2 hh = __floats2half2_rn(a, b);
                h2[c] = *(unsigned int*)&hh;
            }
            uint4* dst = (uint4*)(sm + p * PADC);
            *dst = make_uint4(h2[0], h2[1], h2[2], h2[3]);
            *(unsigned int*)(sm + p * PADC + 8) = h2[4];
        }
    }
    __syncthreads();

    const int nbase = blockIdx.x * RPB + tid;

    #pragma unroll 1
    for (int r = 0; r < RPT; ++r) {
        const int n = nbase + r * TPB;
        if (n >= N) break;

        // ---- Per-roi separable weight setup (branchless, IEEE ops match ref) ----
        const float rsw = rois[n * 5 + 1] * 0.125f;
        const float rsh = rois[n * 5 + 2] * 0.125f;
        const float rew = rois[n * 5 + 3] * 0.125f;
        const float reh = rois[n * 5 + 4] * 0.125f;

        float roi_h = reh - rsh; if (!(roi_h > 0.1f)) roi_h = 0.1f;
        float roi_w = rew - rsw; if (!(roi_w > 0.1f)) roi_w = 0.1f;

        const float bin_h = __fdiv_rn(roi_h, 7.0f);
        const float bin_w = __fdiv_rn(roi_w, 7.0f);
        const float sub_h = 0.25f * bin_h;
        const float sub_w = 0.25f * bin_w;

        const float hstart = floorf(__fadd_rn(rsh, __fmul_rn((float)ph, bin_h)));
        const float wstart = floorf(__fadd_rn(rsw, __fmul_rn((float)pw, bin_w)));
        const int y0i = (int)hstart;
        const int x0i = (int)wstart;

        float gy[3] = {0.f, 0.f, 0.f};
        float gx[3] = {0.f, 0.f, 0.f};
        int cntH = 0, cntW = 0;

        #pragma unroll
        for (int s = 0; s < SP; ++s) {
            const float fs = (float)s + 0.5f;
            {
                const float H = __fadd_rn(hstart, __fmul_rn(fs, sub_h));
                const bool keep = (H > -1.0f) & (H < (float)FH);
                cntH += keep ? 1 : 0;
                const float yf = floorf(H);
                const float dy = H - yf;
                const int y1 = (int)yf;
                const int j  = min(max(y1 - y0i, 0), 1);        // in {0,1}
                const float w1 = (keep && y1 >= 0 && y1 < FH)         ? (1.0f - dy) : 0.0f;
                const float w2 = (keep && y1 + 1 >= 0 && y1 + 1 < FH) ? dy          : 0.0f;
                gy[j]     += w1;
                gy[j + 1] += w2;
            }
            {
                const float W = __fadd_rn(wstart, __fmul_rn(fs, sub_w));
                const bool keep = (W > -1.0f) & (W < (float)FW);
                cntW += keep ? 1 : 0;
                const float xf = floorf(W);
                const float dx = W - xf;
                const int x1 = (int)xf;
                const int i  = min(max(x1 - x0i, 0), 1);        // in {0,1}
                const float w1 = (keep && x1 >= 0 && x1 < FW)         ? (1.0f - dx) : 0.0f;
                const float w2 = (keep && x1 + 1 >= 0 && x1 + 1 < FW) ? dx          : 0.0f;
                gx[i]     += w1;
                gx[i + 1] += w2;
            }
        }
        const float cnt = (float)(cntH * cntW);

        float acc[CH];
        #pragma unroll
        for (int c = 0; c < CH; ++c) acc[c] = 0.f;

        // ---- Branchless 3x3 gather: invalid px always carry weight 0 ----
        const int rowbase = y0i * FW + x0i;
        #pragma unroll
        for (int j = 0; j < 3; ++j) {
            #pragma unroll
            for (int i = 0; i < 3; ++i) {
                const float w = gy[j] * gx[i];
                int pix = rowbase + j * FW + i;
                pix = min(max(pix, 0), NPIX - 1);    // clamp; w==0 if invalid
                const __half* pp = sm + pix * PADC;
                const uint4 v = *(const uint4*)pp;
                const unsigned int v4 = *(const unsigned int*)(pp + 8);
                const float2 f0 = __half22float2(*(const __half2*)&v.x);
                const float2 f1 = __half22float2(*(const __half2*)&v.y);
                const float2 f2 = __half22float2(*(const __half2*)&v.z);
                const float2 f3 = __half22float2(*(const __half2*)&v.w);
                const float2 f4 = __half22float2(*(const __half2*)&v4);
                acc[0] = fmaf(w, f0.x, acc[0]);
                acc[1] = fmaf(w, f0.y, acc[1]);
                acc[2] = fmaf(w, f1.x, acc[2]);
                acc[3] = fmaf(w, f1.y, acc[3]);
                acc[4] = fmaf(w, f2.x, acc[4]);
                acc[5] = fmaf(w, f2.y, acc[5]);
                acc[6] = fmaf(w, f3.x, acc[6]);
                acc[7] = fmaf(w, f3.y, acc[7]);
                acc[8] = fmaf(w, f4.x, acc[8]);
                acc[9] = fmaf(w, f4.y, acc[9]);
            }
        }

        const float inv = (cnt > 0.f) ? __fdiv_rn(1.0f, cnt) : 0.0f;
        float* sc = g_scratch + (size_t)bin * SCRN + n;
        #pragma unroll
        for (int c = 0; c < CH; ++c)
            sc[(size_t)c * (NBINS * SCRN)] = acc[c] * inv;
    }
}

// out[n*490 + q] = scratch[q*SCRN + n]   (q = c*49 + bin)
// Tile: 32 q-rows x 128 n-cols. 256 threads, 16 elems/thread per phase.
#define TQ 32
#define TN 128
#define TS 129   // padded row stride (floats)

__global__ void __launch_bounds__(256) transpose_kernel(
    float* __restrict__ out, int N)
{
    __shared__ float tile[TQ * TS];  // 16.5 KB

    const int tid   = threadIdx.x;
    const int qBase = blockIdx.y * TQ;
    const int nBase = blockIdx.x * TN;

    // ---- Load: lanes = consecutive n (coalesced LDG, conflict-free STS) ----
    {
        const int lane = tid & 31;
        const int qrow = tid >> 5;            // 0..7
        #pragma unroll
        for (int qi = 0; qi < 4; ++qi) {
            const int q  = qrow + qi * 8;     // 0..31
            const int qg = qBase + q;
            if (qg < CH * NBINS) {
                const float* src = g_scratch + (size_t)qg * SCRN + nBase;
                #pragma unroll
                for (int ni = 0; ni < 4; ++ni) {
                    const int nn = lane + ni * 32;          // 0..127
                    tile[q * TS + nn] = src[nn];            // n pad: SCRN covers it
                }
            }
        }
    }
    __syncthreads();

    // ---- Store: half-warp covers 128B contiguous q-span of one n-row ----
    {
        const int c2 = tid & 15;              // float2 column: q = qBase + 2*c2
        const int nr = tid >> 4;              // 0..15
        const int q0 = qBase + 2 * c2;
        #pragma unroll
        for (int k = 0; k < 8; ++k) {
            const int nl = nr + k * 16;       // 0..127
            const int ng = nBase + nl;
            if (ng < N && q0 + 1 < CH * NBINS) {
                float2 v;
                v.x = tile[(2 * c2)     * TS + nl];
                v.y = tile[(2 * c2 + 1) * TS + nl];
                *(float2*)(out + (size_t)ng * (CH * NBINS) + q0) = v;
            }
        }
    }
}

extern "C" void kernel_launch(void* const* d_in, const int* in_sizes, int n_in,
                              void* d_out, int out_size)
{
    const float* ft   = (const float*)d_in[0];   // 490*34*34 floats
    const float* rois = (const float*)d_in[1];   // N*5 floats
    float* out        = (float*)d_out;           // N*10*49 floats

    const int N = in_sizes[1] / 5;

    dim3 grid1((N + RPB - 1) / RPB, NBINS);
    psroi_kernel<<<grid1, TPB>>>(ft, rois, N);

    dim3 grid2((N + TN - 1) / TN, (CH * NBINS + TQ - 1) / TQ);
    transpose_kernel<<<grid2, 256>>>(out, N);
}

// round 4
// speedup vs baseline: 1.1405x; 1.1405x over previous
#include <cuda_runtime.h>
#include <cuda_fp16.h>

#define PH 7
#define PW 7
#define SP 4
#define CH 10
#define FH 34
#define FW 34
#define NPIX (FH * FW)      // 1156
#define NBINS (PH * PW)     // 49
#define TPB 256
#define RPT 4               // rois per thread
#define RPB (TPB * RPT)     // rois per block = 1024
#define PADC 16             // halves per pixel slot (10 used), 32B stride
#define SCRN 10240          // scratch column stride (max N padded)

// 490 x 10240 f32 scratch, layout scratch[(c*49+bin)*SCRN + n]  (~20 MB)
__device__ float g_scratch[CH * NBINS * SCRN];

__global__ void __launch_bounds__(TPB) psroi_kernel(
    const float* __restrict__ ft,     // (C*49, 34, 34)
    const float* __restrict__ rois,   // (N, 5)
    int N)
{
    __shared__ __align__(16) __half sm[NPIX * PADC];   // 36,992 B

    const int bin = blockIdx.y;            // ph*7 + pw
    const int ph  = bin / PW;
    const int pw  = bin - ph * PW;
    const int tid = threadIdx.x;

    // ---- Stage the (ph,pw) slice, all 10 channels, as fp16 [pix][c] ----
    {
        const float* base = ft + (size_t)bin * NPIX;
        for (int p = tid; p < NPIX; p += TPB) {
            unsigned int h2[5];
            #pragma unroll
            for (int c = 0; c < 5; ++c) {
                float a = base[(size_t)(2 * c)     * (NBINS * NPIX) + p];
                float b = base[(size_t)(2 * c + 1) * (NBINS * NPIX) + p];
                __half2 hh = __floats2half2_rn(a, b);
                h2[c] = *(unsigned int*)&hh;
            }
            uint4* dst = (uint4*)(sm + p * PADC);
            *dst = make_uint4(h2[0], h2[1], h2[2], h2[3]);
            *(unsigned int*)(sm + p * PADC + 8) = h2[4];
        }
    }
    __syncthreads();

    const int nbase = blockIdx.x * RPB + tid;

    #pragma unroll 1
    for (int r = 0; r < RPT; ++r) {
        const int n = nbase + r * TPB;
        if (n >= N) break;

        // ---- Per-roi separable weights.
        // Input bounds guarantee: rs* >= 0, re* <= 33.625 < 34, so every
        // sample is in (-1, F*): keep == true, count == 16, and the lower
        // bilinear corner (y1, x1) is always in-range. Only the upper
        // corner (y1+1 / x1+1) can fall off the far edge.
        const float rsw = rois[n * 5 + 1] * 0.125f;
        const float rsh = rois[n * 5 + 2] * 0.125f;
        const float rew = rois[n * 5 + 3] * 0.125f;
        const float reh = rois[n * 5 + 4] * 0.125f;

        float roi_h = reh - rsh; if (!(roi_h > 0.1f)) roi_h = 0.1f;
        float roi_w = rew - rsw; if (!(roi_w > 0.1f)) roi_w = 0.1f;

        const float bin_h = __fdiv_rn(roi_h, 7.0f);   // exact rn div matches ref
        const float bin_w = __fdiv_rn(roi_w, 7.0f);
        const float sub_h = 0.25f * bin_h;
        const float sub_w = 0.25f * bin_w;

        const float hstart = floorf(__fadd_rn(rsh, __fmul_rn((float)ph, bin_h)));
        const float wstart = floorf(__fadd_rn(rsw, __fmul_rn((float)pw, bin_w)));
        const int y0i = (int)hstart;
        const int x0i = (int)wstart;

        float gy[3] = {0.f, 0.f, 0.f};
        float gx[3] = {0.f, 0.f, 0.f};

        #pragma unroll
        for (int s = 0; s < SP; ++s) {
            const float fs = (float)s + 0.5f;
            {
                const float H = __fadd_rn(hstart, __fmul_rn(fs, sub_h));
                const float yf = floorf(H);
                const float dy = H - yf;
                const int y1 = (int)yf;
                const int j  = y1 - y0i;                 // in {0,1}: hstart integer, fs*sub < 2
                const float w2 = (y1 + 1 < FH) ? dy : 0.0f;
                gy[j]     += 1.0f - dy;
                gy[j + 1] += w2;
            }
            {
                const float W = __fadd_rn(wstart, __fmul_rn(fs, sub_w));
                const float xf = floorf(W);
                const float dx = W - xf;
                const int x1 = (int)xf;
                const int i  = x1 - x0i;                 // in {0,1}
                const float w2 = (x1 + 1 < FW) ? dx : 0.0f;
                gx[i]     += 1.0f - dx;
                gx[i + 1] += w2;
            }
        }
        // fold 1/count = 1/16 (exact) into gy
        gy[0] *= 0.0625f; gy[1] *= 0.0625f; gy[2] *= 0.0625f;

        float acc[CH];
        #pragma unroll
        for (int c = 0; c < CH; ++c) acc[c] = 0.f;

        // ---- Zero-skip 3x3 gather; w != 0 implies the pixel is in-range ----
        const int rowbase = y0i * FW + x0i;
        #pragma unroll
        for (int j = 0; j < 3; ++j) {
            const float gyj = gy[j];
            if (gyj != 0.f) {
                const int off = rowbase + j * FW;
                #pragma unroll
                for (int i = 0; i < 3; ++i) {
                    const float w = gyj * gx[i];
                    if (w != 0.f) {
                        const __half* pp = sm + (off + i) * PADC;
                        const uint4 v = *(const uint4*)pp;
                        const unsigned int v4 = *(const unsigned int*)(pp + 8);
                        const float2 f0 = __half22float2(*(const __half2*)&v.x);
                        const float2 f1 = __half22float2(*(const __half2*)&v.y);
                        const float2 f2 = __half22float2(*(const __half2*)&v.z);
                        const float2 f3 = __half22float2(*(const __half2*)&v.w);
                        const float2 f4 = __half22float2(*(const __half2*)&v4);
                        acc[0] = fmaf(w, f0.x, acc[0]);
                        acc[1] = fmaf(w, f0.y, acc[1]);
                        acc[2] = fmaf(w, f1.x, acc[2]);
                        acc[3] = fmaf(w, f1.y, acc[3]);
                        acc[4] = fmaf(w, f2.x, acc[4]);
                        acc[5] = fmaf(w, f2.y, acc[5]);
                        acc[6] = fmaf(w, f3.x, acc[6]);
                        acc[7] = fmaf(w, f3.y, acc[7]);
                        acc[8] = fmaf(w, f4.x, acc[8]);
                        acc[9] = fmaf(w, f4.y, acc[9]);
                    }
                }
            }
        }

        float* sc = g_scratch + (size_t)bin * SCRN + n;
        #pragma unroll
        for (int c = 0; c < CH; ++c)
            sc[(size_t)c * (NBINS * SCRN)] = acc[c];
    }
}

// out[n*490 + q] = scratch[q*SCRN + n]   (q = c*49 + bin)
// Tile: 32 q-rows x 256 n-cols. 256 threads, 32 elems/thread per phase.
#define TQ 32
#define TN 256
#define TS 257   // padded row stride (floats)

__global__ void __launch_bounds__(256) transpose_kernel(
    float* __restrict__ out, int N)
{
    __shared__ float tile[TQ * TS];  // 32.9 KB

    const int tid   = threadIdx.x;
    const int qBase = blockIdx.y * TQ;
    const int nBase = blockIdx.x * TN;

    // ---- Load: lanes = consecutive n (coalesced LDG, conflict-free STS) ----
    {
        const int lane = tid & 31;
        const int qrow = tid >> 5;            // 0..7
        #pragma unroll
        for (int qi = 0; qi < 4; ++qi) {
            const int q  = qrow + qi * 8;     // 0..31
            const int qg = qBase + q;
            if (qg < CH * NBINS) {
                const float* src = g_scratch + (size_t)qg * SCRN + nBase;
                #pragma unroll
                for (int ni = 0; ni < 8; ++ni) {
                    const int nn = lane + ni * 32;          // 0..255
                    tile[q * TS + nn] = src[nn];            // SCRN pad covers n tail
                }
            }
        }
    }
    __syncthreads();

    // ---- Store: half-warp covers 128B contiguous q-span of one n-row ----
    {
        const int c2 = tid & 15;              // float2 column: q = qBase + 2*c2
        const int nr = tid >> 4;              // 0..15
        const int q0 = qBase + 2 * c2;
        if (q0 + 1 < CH * NBINS) {
            #pragma unroll
            for (int k = 0; k < 16; ++k) {
                const int nl = nr + k * 16;   // 0..255
                const int ng = nBase + nl;
                if (ng < N) {
                    float2 v;
                    v.x = tile[(2 * c2)     * TS + nl];
                    v.y = tile[(2 * c2 + 1) * TS + nl];
                    *(float2*)(out + (size_t)ng * (CH * NBINS) + q0) = v;
                }
            }
        }
    }
}

extern "C" void kernel_launch(void* const* d_in, const int* in_sizes, int n_in,
                              void* d_out, int out_size)
{
    const float* ft   = (const float*)d_in[0];   // 490*34*34 floats
    const float* rois = (const float*)d_in[1];   // N*5 floats
    float* out        = (float*)d_out;           // N*10*49 floats

    const int N = in_sizes[1] / 5;

    dim3 grid1((N + RPB - 1) / RPB, NBINS);
    psroi_kernel<<<grid1, TPB>>>(ft, rois, N);

    dim3 grid2((N + TN - 1) / TN, (CH * NBINS + TQ - 1) / TQ);
    transpose_kernel<<<grid2, 256>>>(out, N);
}